// round 1
// baseline (speedup 1.0000x reference)
#include <cuda_runtime.h>
#include <math.h>

#define BB 8
#define TT 2048
#define EE 1024
#define DD 128
#define BT (BB*TT)

// Scratch for projected Q/K/V (no device allocation allowed -> __device__ globals)
__device__ float g_q[BT*DD];
__device__ float g_k[BT*DD];
__device__ float g_v[BT*DD];

// ---------------------------------------------------------------------------
// Kernel 1: fused QKV projection.  out = x @ W  for each of Wq/Wk/Wv.
// M=16384, K=1024, N=128. 128x128 tile per block, BK=16, 8x8 per thread.
// ---------------------------------------------------------------------------
__global__ __launch_bounds__(256) void proj_kernel(const float* __restrict__ x,
                                                   const float* __restrict__ Wk,
                                                   const float* __restrict__ Wq,
                                                   const float* __restrict__ Wv)
{
    __shared__ float As[16][132];   // A tile transposed: As[k][m], padded
    __shared__ float Bs[16][132];   // B tile: Bs[k][n], padded

    const int tid = threadIdx.x;
    const int ty = tid >> 4;        // 0..15
    const int tx = tid & 15;        // 0..15
    const int m0 = blockIdx.x * 128;
    const int z  = blockIdx.y;      // 0:q 1:k 2:v

    const float* W  = (z == 0) ? Wq : (z == 1) ? Wk : Wv;
    float*       out = (z == 0) ? g_q : (z == 1) ? g_k : g_v;

    float acc[8][8];
#pragma unroll
    for (int i = 0; i < 8; ++i)
#pragma unroll
        for (int j = 0; j < 8; ++j) acc[i][j] = 0.f;

    for (int k0 = 0; k0 < EE; k0 += 16) {
        // Load A tile (x rows m0..m0+127, k-cols k0..k0+15), store transposed.
#pragma unroll
        for (int it = 0; it < 2; ++it) {
            int linear = tid + it * 256;       // 0..511
            int row = linear >> 2;             // 0..127
            int g   = linear & 3;              // 0..3
            float4 v = *(const float4*)&x[(size_t)(m0 + row) * EE + k0 + 4 * g];
            As[4*g+0][row] = v.x;
            As[4*g+1][row] = v.y;
            As[4*g+2][row] = v.z;
            As[4*g+3][row] = v.w;
        }
        // Load B tile (W rows k0..k0+15, all 128 cols).
#pragma unroll
        for (int it = 0; it < 2; ++it) {
            int linear = tid + it * 256;       // 0..511
            int r = linear >> 5;               // 0..15
            int g = linear & 31;               // 0..31
            *(float4*)&Bs[r][4*g] = *(const float4*)&W[(size_t)(k0 + r) * DD + 4 * g];
        }
        __syncthreads();

#pragma unroll
        for (int kk = 0; kk < 16; ++kk) {
            float4 a0 = *(const float4*)&As[kk][4*ty];
            float4 a1 = *(const float4*)&As[kk][64 + 4*ty];
            float4 b0 = *(const float4*)&Bs[kk][4*tx];
            float4 b1 = *(const float4*)&Bs[kk][64 + 4*tx];
            float a[8] = {a0.x,a0.y,a0.z,a0.w,a1.x,a1.y,a1.z,a1.w};
            float b[8] = {b0.x,b0.y,b0.z,b0.w,b1.x,b1.y,b1.z,b1.w};
#pragma unroll
            for (int i = 0; i < 8; ++i)
#pragma unroll
                for (int j = 0; j < 8; ++j)
                    acc[i][j] += a[i] * b[j];
        }
        __syncthreads();
    }

#pragma unroll
    for (int i = 0; i < 8; ++i) {
        int m = m0 + ((i < 4) ? (4*ty + i) : (64 + 4*ty + i - 4));
        float4 o0 = make_float4(acc[i][0], acc[i][1], acc[i][2], acc[i][3]);
        float4 o1 = make_float4(acc[i][4], acc[i][5], acc[i][6], acc[i][7]);
        *(float4*)&out[(size_t)m * DD +      4*tx] = o0;
        *(float4*)&out[(size_t)m * DD + 64 + 4*tx] = o1;
    }
}

// ---------------------------------------------------------------------------
// Kernel 2: causal flash attention.
// Block = one (batch, 64-row query tile). 256 threads as 16x16.
// Thread (ty,tx): S rows 4ty..4ty+3, S cols 4tx..4tx+3;
//                 O rows 4ty..4ty+3, O cols {4tx..4tx+3} U {64+4tx..64+4tx+3}.
// Smem: Qs[64][128] natural, Ks[64][128] float4-XOR-swizzled, Vs[64][128]
// natural, Ps[64][65] padded. ~113 KB dynamic.
// ---------------------------------------------------------------------------
__global__ __launch_bounds__(256) void attn_kernel(float* __restrict__ out)
{
    extern __shared__ float smem[];
    float4* Qs = (float4*)smem;                    // 64*32 float4
    float4* Ks = (float4*)(smem + 64*128);         // swizzled
    float4* Vs = (float4*)(smem + 2*64*128);
    float*  Ps = smem + 3*64*128;                  // 64*65 floats

    const int tid = threadIdx.x;
    const int ty = tid >> 4;
    const int tx = tid & 15;
    const int qt = blockIdx.x;
    const int b  = blockIdx.y;
    const int t0 = qt * 64;
    const size_t base = (size_t)b * TT;

    const float4* gq = (const float4*)g_q;
    const float4* gk = (const float4*)g_k;
    const float4* gv = (const float4*)g_v;

    // Load Q tile once.
    for (int idx = tid; idx < 64*32; idx += 256) {
        int row = idx >> 5, g = idx & 31;
        Qs[row*32 + g] = gq[(base + t0 + row)*32 + g];
    }

    float acc[4][8];
#pragma unroll
    for (int i = 0; i < 4; ++i)
#pragma unroll
        for (int c = 0; c < 8; ++c) acc[i][c] = 0.f;
    float mrow[4], lrow[4];
#pragma unroll
    for (int i = 0; i < 4; ++i) { mrow[i] = -INFINITY; lrow[i] = 0.f; }

    const float scale = 0.08838834764831845f;   // 1/sqrt(128)
    const int sw = tx & 7;

    for (int s0 = 0; s0 <= t0; s0 += 64) {
        // Load K (XOR-swizzled on float4 index) and V (natural).
        for (int idx = tid; idx < 64*32; idx += 256) {
            int row = idx >> 5, g = idx & 31;
            Ks[row*32 + (g ^ ((row >> 2) & 7))] = gk[(base + s0 + row)*32 + g];
            Vs[row*32 + g]                      = gv[(base + s0 + row)*32 + g];
        }
        __syncthreads();

        // S = Q K^T for this tile (per-thread 4x4).
        float s[4][4];
#pragma unroll
        for (int i = 0; i < 4; ++i)
#pragma unroll
            for (int j = 0; j < 4; ++j) s[i][j] = 0.f;

#pragma unroll 4
        for (int g = 0; g < 32; ++g) {
            float4 q[4], k[4];
#pragma unroll
            for (int i = 0; i < 4; ++i) q[i] = Qs[(4*ty + i)*32 + g];
#pragma unroll
            for (int j = 0; j < 4; ++j) k[j] = Ks[(4*tx + j)*32 + (g ^ sw)];
#pragma unroll
            for (int i = 0; i < 4; ++i)
#pragma unroll
                for (int j = 0; j < 4; ++j)
                    s[i][j] += q[i].x*k[j].x + q[i].y*k[j].y
                             + q[i].z*k[j].z + q[i].w*k[j].w;
        }

        // Online softmax update.
        const bool diag = (s0 == t0);
#pragma unroll
        for (int i = 0; i < 4; ++i) {
            int row = 4*ty + i;
            float mx = -INFINITY;
#pragma unroll
            for (int j = 0; j < 4; ++j) {
                float v = s[i][j] * scale;
                if (diag && (4*tx + j) > row) v = -INFINITY;
                s[i][j] = v;
                mx = fmaxf(mx, v);
            }
#pragma unroll
            for (int off = 8; off > 0; off >>= 1)
                mx = fmaxf(mx, __shfl_xor_sync(0xffffffffu, mx, off));
            float m_new = fmaxf(mrow[i], mx);
            float alpha = __expf(mrow[i] - m_new);
            float rsum = 0.f;
            float p[4];
#pragma unroll
            for (int j = 0; j < 4; ++j) {
                p[j] = __expf(s[i][j] - m_new);
                rsum += p[j];
            }
#pragma unroll
            for (int off = 8; off > 0; off >>= 1)
                rsum += __shfl_xor_sync(0xffffffffu, rsum, off);
            lrow[i] = lrow[i] * alpha + rsum;
            mrow[i] = m_new;
#pragma unroll
            for (int c = 0; c < 8; ++c) acc[i][c] *= alpha;
#pragma unroll
            for (int j = 0; j < 4; ++j) Ps[row*65 + 4*tx + j] = p[j];
        }
        __syncthreads();

        // O += P @ V
#pragma unroll 2
        for (int sI = 0; sI < 64; ++sI) {
            float4 va = Vs[sI*32 + tx];
            float4 vb = Vs[sI*32 + 16 + tx];
#pragma unroll
            for (int i = 0; i < 4; ++i) {
                float pv = Ps[(4*ty + i)*65 + sI];
                acc[i][0] += pv * va.x;
                acc[i][1] += pv * va.y;
                acc[i][2] += pv * va.z;
                acc[i][3] += pv * va.w;
                acc[i][4] += pv * vb.x;
                acc[i][5] += pv * vb.y;
                acc[i][6] += pv * vb.z;
                acc[i][7] += pv * vb.w;
            }
        }
        __syncthreads();
    }

    // Epilogue: normalize and store.
#pragma unroll
    for (int i = 0; i < 4; ++i) {
        float inv = 1.f / lrow[i];
        size_t row = base + t0 + 4*ty + i;
        float4 o0 = make_float4(acc[i][0]*inv, acc[i][1]*inv, acc[i][2]*inv, acc[i][3]*inv);
        float4 o1 = make_float4(acc[i][4]*inv, acc[i][5]*inv, acc[i][6]*inv, acc[i][7]*inv);
        *(float4*)&out[row * DD +      4*tx] = o0;
        *(float4*)&out[row * DD + 64 + 4*tx] = o1;
    }
}

// ---------------------------------------------------------------------------
extern "C" void kernel_launch(void* const* d_in, const int* in_sizes, int n_in,
                              void* d_out, int out_size)
{
    (void)in_sizes; (void)n_in; (void)out_size;
    const float* x  = (const float*)d_in[0];
    const float* Wk = (const float*)d_in[1];
    const float* Wq = (const float*)d_in[2];
    const float* Wv = (const float*)d_in[3];
    float* out = (float*)d_out;

    // Projections: grid (M/128, 3)
    dim3 pgrid(BT/128, 3);
    proj_kernel<<<pgrid, 256>>>(x, Wk, Wq, Wv);

    // Attention: grid (T/64, B), ~113KB dynamic smem
    const int smem_bytes = (3*64*128 + 64*65) * (int)sizeof(float);
    cudaFuncSetAttribute(attn_kernel,
                         cudaFuncAttributeMaxDynamicSharedMemorySize, smem_bytes);
    dim3 agrid(TT/64, BB);
    attn_kernel<<<agrid, 256, smem_bytes>>>(out);
}

// round 2
// speedup vs baseline: 3.3984x; 3.3984x over previous
#include <cuda_runtime.h>
#include <math.h>

#define BB 8
#define TT 2048
#define EE 1024
#define DD 128
#define BT (BB*TT)

// Scratch for projected Q/K/V
__device__ float g_q[BT*DD];
__device__ float g_k[BT*DD];
__device__ float g_v[BT*DD];

__device__ __forceinline__ unsigned f2tf(float x) {
    unsigned u;
    asm("cvt.rna.tf32.f32 %0, %1;" : "=r"(u) : "f"(x));
    return u;
}

__device__ __forceinline__ void mma8(float* d, const unsigned* a, const unsigned* b) {
    asm volatile(
        "mma.sync.aligned.m16n8k8.row.col.f32.tf32.tf32.f32 "
        "{%0,%1,%2,%3}, {%4,%5,%6,%7}, {%8,%9}, {%0,%1,%2,%3};\n"
        : "+f"(d[0]), "+f"(d[1]), "+f"(d[2]), "+f"(d[3])
        : "r"(a[0]), "r"(a[1]), "r"(a[2]), "r"(a[3]), "r"(b[0]), "r"(b[1]));
}

// ---------------------------------------------------------------------------
// Kernel 1: QKV projection, tf32 mma. out = x @ W  (M=16384, K=1024, N=128).
// Block tile 128x128, 8 warps (2m x 4n), warp tile 64x32, BK=32.
// ---------------------------------------------------------------------------
#define AP 36   // A smem stride (== 4 mod 32)
#define BP 136  // B smem stride (== 8 mod 32)

__global__ __launch_bounds__(256) void proj_kernel(const float* __restrict__ x,
                                                   const float* __restrict__ Wk,
                                                   const float* __restrict__ Wq,
                                                   const float* __restrict__ Wv)
{
    __shared__ unsigned As[128 * AP];
    __shared__ unsigned Bs[32 * BP];

    const int tid = threadIdx.x;
    const int wid = tid >> 5;
    const int lane = tid & 31;
    const int r = lane >> 2;   // 0..7
    const int c = lane & 3;    // 0..3
    const int mi = wid >> 2;   // 0..1
    const int nj = wid & 3;    // 0..3
    const int m0 = blockIdx.x * 128;
    const int z = blockIdx.y;

    const float* W  = (z == 0) ? Wq : (z == 1) ? Wk : Wv;
    float*      out = (z == 0) ? g_q : (z == 1) ? g_k : g_v;

    float acc[4][4][4];
#pragma unroll
    for (int mt = 0; mt < 4; ++mt)
#pragma unroll
        for (int nt = 0; nt < 4; ++nt)
#pragma unroll
            for (int f = 0; f < 4; ++f) acc[mt][nt][f] = 0.f;

    for (int k0 = 0; k0 < EE; k0 += 32) {
        // A tile: 128 rows x 32 cols of x
#pragma unroll
        for (int it = 0; it < 4; ++it) {
            int linear = tid + 256 * it;       // 0..1023
            int m = linear >> 3;               // 0..127
            int g = linear & 7;                // 0..7
            float4 v = *(const float4*)&x[(size_t)(m0 + m) * EE + k0 + 4 * g];
            uint4 u = make_uint4(f2tf(v.x), f2tf(v.y), f2tf(v.z), f2tf(v.w));
            *(uint4*)&As[m * AP + 4 * g] = u;
        }
        // B tile: 32 rows x 128 cols of W
#pragma unroll
        for (int it = 0; it < 4; ++it) {
            int linear = tid + 256 * it;
            int k = linear >> 5;               // 0..31
            int g = linear & 31;               // 0..31
            float4 v = *(const float4*)&W[(size_t)(k0 + k) * DD + 4 * g];
            uint4 u = make_uint4(f2tf(v.x), f2tf(v.y), f2tf(v.z), f2tf(v.w));
            *(uint4*)&Bs[k * BP + 4 * g] = u;
        }
        __syncthreads();

#pragma unroll
        for (int kk = 0; kk < 4; ++kk) {
            unsigned a[4][4], b[4][2];
#pragma unroll
            for (int mt = 0; mt < 4; ++mt) {
                int R = 64 * mi + 16 * mt;
                a[mt][0] = As[(R + r) * AP + 8 * kk + c];
                a[mt][1] = As[(R + r + 8) * AP + 8 * kk + c];
                a[mt][2] = As[(R + r) * AP + 8 * kk + c + 4];
                a[mt][3] = As[(R + r + 8) * AP + 8 * kk + c + 4];
            }
#pragma unroll
            for (int nt = 0; nt < 4; ++nt) {
                int N = 32 * nj + 8 * nt;
                b[nt][0] = Bs[(8 * kk + c) * BP + N + r];
                b[nt][1] = Bs[(8 * kk + c + 4) * BP + N + r];
            }
#pragma unroll
            for (int mt = 0; mt < 4; ++mt)
#pragma unroll
                for (int nt = 0; nt < 4; ++nt)
                    mma8(acc[mt][nt], a[mt], b[nt]);
        }
        __syncthreads();
    }

#pragma unroll
    for (int mt = 0; mt < 4; ++mt) {
        int row0 = m0 + 64 * mi + 16 * mt + r;
#pragma unroll
        for (int nt = 0; nt < 4; ++nt) {
            int col = 32 * nj + 8 * nt + 2 * c;
            *(float2*)&out[(size_t)row0 * DD + col] =
                make_float2(acc[mt][nt][0], acc[mt][nt][1]);
            *(float2*)&out[(size_t)(row0 + 8) * DD + col] =
                make_float2(acc[mt][nt][2], acc[mt][nt][3]);
        }
    }
}

// ---------------------------------------------------------------------------
// Kernel 2: causal flash attention with tf32 mma.
// Br=Bc=64, 8 warps: mi = wid&3 (16-row m slice), ni = wid>>2 (n half).
// Q fragments live in registers (scale pre-folded). K/V/P staged in smem.
// ---------------------------------------------------------------------------
#define KP 132  // K smem stride (== 4 mod 32)
#define VP 136  // V smem stride (== 8 mod 32)
#define PP 68   // P smem stride (== 4 mod 32)

__global__ __launch_bounds__(256) void attn_kernel(float* __restrict__ out)
{
    extern __shared__ unsigned sm[];
    unsigned* Ks = sm;                      // 64*KP
    unsigned* Vs = Ks + 64 * KP;            // 64*VP
    unsigned* Ps = Vs + 64 * VP;            // 64*PP
    float* smax = (float*)(Ps + 64 * PP);   // 128
    float* ssum = smax + 128;               // 128

    const int tid = threadIdx.x;
    const int wid = tid >> 5;
    const int lane = tid & 31;
    const int r = lane >> 2;
    const int c = lane & 3;
    const int mi = wid & 3;
    const int ni = wid >> 2;

    const int bid = blockIdx.x;
    const int qt = (TT / 64 - 1) - (bid >> 3);  // heavy tiles first
    const int b = bid & 7;
    const int t0 = qt * 64;
    const size_t base = (size_t)b * TT;

    const float scale = 0.08838834764831845f;  // 1/sqrt(128)
    const int lr = 16 * mi + r;

    // ---- stage Q through Ks, extract A fragments (scale folded in) ----
#pragma unroll
    for (int it = 0; it < 8; ++it) {
        int linear = tid + 256 * it;           // 0..2047
        int row = linear >> 5;                 // 0..63
        int g = linear & 31;
        float4 v = *(const float4*)&g_q[(base + t0 + row) * DD + 4 * g];
        uint4 u = make_uint4(f2tf(v.x * scale), f2tf(v.y * scale),
                             f2tf(v.z * scale), f2tf(v.w * scale));
        *(uint4*)&Ks[row * KP + 4 * g] = u;
    }
    __syncthreads();

    unsigned qa[16][4];
#pragma unroll
    for (int kc = 0; kc < 16; ++kc) {
        qa[kc][0] = Ks[lr * KP + 8 * kc + c];
        qa[kc][1] = Ks[(lr + 8) * KP + 8 * kc + c];
        qa[kc][2] = Ks[lr * KP + 8 * kc + c + 4];
        qa[kc][3] = Ks[(lr + 8) * KP + 8 * kc + c + 4];
    }
    __syncthreads();

    float oacc[8][4];
#pragma unroll
    for (int nt = 0; nt < 8; ++nt)
#pragma unroll
        for (int f = 0; f < 4; ++f) oacc[nt][f] = 0.f;
    float m_run[2] = {-INFINITY, -INFINITY};
    float l_run[2] = {0.f, 0.f};

    for (int s0 = 0; s0 <= t0; s0 += 64) {
        // ---- load K, V tiles ----
#pragma unroll
        for (int it = 0; it < 8; ++it) {
            int linear = tid + 256 * it;
            int row = linear >> 5;
            int g = linear & 31;
            float4 kv = *(const float4*)&g_k[(base + s0 + row) * DD + 4 * g];
            float4 vv = *(const float4*)&g_v[(base + s0 + row) * DD + 4 * g];
            *(uint4*)&Ks[row * KP + 4 * g] =
                make_uint4(f2tf(kv.x), f2tf(kv.y), f2tf(kv.z), f2tf(kv.w));
            *(uint4*)&Vs[row * VP + 4 * g] =
                make_uint4(f2tf(vv.x), f2tf(vv.y), f2tf(vv.z), f2tf(vv.w));
        }
        __syncthreads();

        // ---- S = (Q*scale) K^T : warp computes 16 rows x 32 cols ----
        float sacc[4][4];
#pragma unroll
        for (int nt = 0; nt < 4; ++nt)
#pragma unroll
            for (int f = 0; f < 4; ++f) sacc[nt][f] = 0.f;

#pragma unroll
        for (int kc = 0; kc < 16; ++kc) {
            unsigned kb[4][2];
#pragma unroll
            for (int nt = 0; nt < 4; ++nt) {
                int n = 32 * ni + 8 * nt + r;
                kb[nt][0] = Ks[n * KP + 8 * kc + c];
                kb[nt][1] = Ks[n * KP + 8 * kc + c + 4];
            }
#pragma unroll
            for (int nt = 0; nt < 4; ++nt)
                mma8(sacc[nt], qa[kc], kb[nt]);
        }

        // ---- causal mask (diagonal tile only) ----
        if (s0 == t0) {
#pragma unroll
            for (int nt = 0; nt < 4; ++nt)
#pragma unroll
                for (int f = 0; f < 4; ++f) {
                    int row = lr + ((f >= 2) ? 8 : 0);
                    int col = 32 * ni + 8 * nt + 2 * c + (f & 1);
                    if (col > row) sacc[nt][f] = -1e30f;
                }
        }

        // ---- partial row max ----
        float pmax[2];
#pragma unroll
        for (int h = 0; h < 2; ++h) {
            float mx = -INFINITY;
#pragma unroll
            for (int nt = 0; nt < 4; ++nt) {
                mx = fmaxf(mx, sacc[nt][2 * h]);
                mx = fmaxf(mx, sacc[nt][2 * h + 1]);
            }
            mx = fmaxf(mx, __shfl_xor_sync(0xffffffffu, mx, 1));
            mx = fmaxf(mx, __shfl_xor_sync(0xffffffffu, mx, 2));
            pmax[h] = mx;
        }
        if (c == 0) {
            smax[ni * 64 + lr] = pmax[0];
            smax[ni * 64 + lr + 8] = pmax[1];
        }
        __syncthreads();

        float m_new[2], alpha[2], psum[2];
#pragma unroll
        for (int h = 0; h < 2; ++h) {
            float mt_ = fmaxf(smax[lr + 8 * h], smax[64 + lr + 8 * h]);
            m_new[h] = fmaxf(m_run[h], mt_);
            alpha[h] = __expf(m_run[h] - m_new[h]);
            m_run[h] = m_new[h];
        }

        // ---- exp, write P (tf32), partial row sum ----
#pragma unroll
        for (int h = 0; h < 2; ++h) {
            float s_ = 0.f;
#pragma unroll
            for (int nt = 0; nt < 4; ++nt) {
                float p0 = __expf(sacc[nt][2 * h] - m_new[h]);
                float p1 = __expf(sacc[nt][2 * h + 1] - m_new[h]);
                s_ += p0 + p1;
                *(uint2*)&Ps[(lr + 8 * h) * PP + 32 * ni + 8 * nt + 2 * c] =
                    make_uint2(f2tf(p0), f2tf(p1));
            }
            s_ += __shfl_xor_sync(0xffffffffu, s_, 1);
            s_ += __shfl_xor_sync(0xffffffffu, s_, 2);
            psum[h] = s_;
        }
        if (c == 0) {
            ssum[ni * 64 + lr] = psum[0];
            ssum[ni * 64 + lr + 8] = psum[1];
        }
        __syncthreads();

#pragma unroll
        for (int h = 0; h < 2; ++h)
            l_run[h] = l_run[h] * alpha[h] + ssum[lr + 8 * h] + ssum[64 + lr + 8 * h];

        // ---- rescale O ----
#pragma unroll
        for (int nt = 0; nt < 8; ++nt) {
            oacc[nt][0] *= alpha[0];
            oacc[nt][1] *= alpha[0];
            oacc[nt][2] *= alpha[1];
            oacc[nt][3] *= alpha[1];
        }

        // ---- O += P V : warp computes 16 rows x 64 cols (n half = ni) ----
#pragma unroll
        for (int kc2 = 0; kc2 < 8; ++kc2) {
            unsigned pa[4];
            pa[0] = Ps[lr * PP + 8 * kc2 + c];
            pa[1] = Ps[(lr + 8) * PP + 8 * kc2 + c];
            pa[2] = Ps[lr * PP + 8 * kc2 + c + 4];
            pa[3] = Ps[(lr + 8) * PP + 8 * kc2 + c + 4];
#pragma unroll
            for (int nt = 0; nt < 8; ++nt) {
                unsigned vb[2];
                int n = 64 * ni + 8 * nt + r;
                vb[0] = Vs[(8 * kc2 + c) * VP + n];
                vb[1] = Vs[(8 * kc2 + c + 4) * VP + n];
                mma8(oacc[nt], pa, vb);
            }
        }
        __syncthreads();  // protect K/V/P for next iteration
    }

    // ---- epilogue ----
    float inv0 = 1.f / l_run[0];
    float inv1 = 1.f / l_run[1];
#pragma unroll
    for (int nt = 0; nt < 8; ++nt) {
        int col = 64 * ni + 8 * nt + 2 * c;
        size_t row0 = base + t0 + lr;
        *(float2*)&out[row0 * DD + col] =
            make_float2(oacc[nt][0] * inv0, oacc[nt][1] * inv0);
        *(float2*)&out[(row0 + 8) * DD + col] =
            make_float2(oacc[nt][2] * inv1, oacc[nt][3] * inv1);
    }
}

// ---------------------------------------------------------------------------
extern "C" void kernel_launch(void* const* d_in, const int* in_sizes, int n_in,
                              void* d_out, int out_size)
{
    (void)in_sizes; (void)n_in; (void)out_size;
    const float* x  = (const float*)d_in[0];
    const float* Wk = (const float*)d_in[1];
    const float* Wq = (const float*)d_in[2];
    const float* Wv = (const float*)d_in[3];
    float* out = (float*)d_out;

    dim3 pgrid(BT / 128, 3);
    proj_kernel<<<pgrid, 256>>>(x, Wk, Wq, Wv);

    const int smem_bytes = (64 * KP + 64 * VP + 64 * PP) * 4 + 256 * 4;
    cudaFuncSetAttribute(attn_kernel,
                         cudaFuncAttributeMaxDynamicSharedMemorySize, smem_bytes);
    attn_kernel<<<TT / 64 * BB, 256, smem_bytes>>>(out);
}

// round 3
// speedup vs baseline: 3.9943x; 1.1753x over previous
#include <cuda_runtime.h>
#include <math.h>

#define BB 8
#define TT 2048
#define EE 1024
#define DD 128
#define BT (BB*TT)

// Device scratch (no allocations allowed)
__device__ float g_xt[BT*EE];      // x rounded to tf32
__device__ float g_wt[3*EE*DD];    // Wq,Wk,Wv rounded to tf32 (z=0:q 1:k 2:v)
__device__ float g_q[BT*DD];       // q*scale, tf32-rounded
__device__ float g_k[BT*DD];       // tf32-rounded
__device__ float g_v[BT*DD];       // tf32-rounded

__device__ __forceinline__ unsigned f2tf(float x) {
    unsigned u;
    asm("cvt.rna.tf32.f32 %0, %1;" : "=r"(u) : "f"(x));
    return u;
}
__device__ __forceinline__ float f2tff(float x) { return __uint_as_float(f2tf(x)); }

__device__ __forceinline__ void cpa16(unsigned* dst, const void* src) {
    unsigned d = (unsigned)__cvta_generic_to_shared(dst);
    asm volatile("cp.async.cg.shared.global [%0], [%1], 16;\n" :: "r"(d), "l"(src));
}
__device__ __forceinline__ void cp_commit() { asm volatile("cp.async.commit_group;\n"); }
template<int N> __device__ __forceinline__ void cp_wait() {
    asm volatile("cp.async.wait_group %0;\n" :: "n"(N));
}

__device__ __forceinline__ void mma8(float* d, const unsigned* a, const unsigned* b) {
    asm volatile(
        "mma.sync.aligned.m16n8k8.row.col.f32.tf32.tf32.f32 "
        "{%0,%1,%2,%3}, {%4,%5,%6,%7}, {%8,%9}, {%0,%1,%2,%3};\n"
        : "+f"(d[0]), "+f"(d[1]), "+f"(d[2]), "+f"(d[3])
        : "r"(a[0]), "r"(a[1]), "r"(a[2]), "r"(a[3]), "r"(b[0]), "r"(b[1]));
}

// ---------------------------------------------------------------------------
// Kernel 0: elementwise tf32 pre-round of x and the three W matrices.
// ---------------------------------------------------------------------------
__global__ __launch_bounds__(256) void cvt_kernel(const float* __restrict__ x,
                                                  const float* __restrict__ Wk,
                                                  const float* __restrict__ Wq,
                                                  const float* __restrict__ Wv)
{
    const int NX = BT*EE/4;
    const int NW = EE*DD/4;
    int i = blockIdx.x * 256 + threadIdx.x;
    if (i < NX) {
        float4 v = ((const float4*)x)[i];
        ((float4*)g_xt)[i] = make_float4(f2tff(v.x), f2tff(v.y), f2tff(v.z), f2tff(v.w));
    } else {
        int j = i - NX;
        if (j < 3*NW) {
            int z = j / NW, p = j - z*NW;
            const float4* src = (const float4*)((z == 0) ? Wq : (z == 1) ? Wk : Wv);
            float4 v = src[p];
            ((float4*)g_wt)[z*NW + p] =
                make_float4(f2tff(v.x), f2tff(v.y), f2tff(v.z), f2tff(v.w));
        }
    }
}

// ---------------------------------------------------------------------------
// Kernel 1: QKV projection, tf32 mma, 3-stage cp.async pipeline.
// Block tile 128x128, 8 warps (2m x 4n), warp tile 64x32, BK=32.
// ---------------------------------------------------------------------------
#define AP 36   // A smem stride (== 4 mod 32)
#define BP 136  // B smem stride (== 8 mod 32)
#define A_ST (128*AP)
#define B_ST (32*BP)

__global__ __launch_bounds__(256) void proj_kernel()
{
    extern __shared__ unsigned psm[];
    unsigned* As = psm;                // 3 stages of A
    unsigned* Bs = psm + 3*A_ST;       // 3 stages of B

    const int tid = threadIdx.x;
    const int wid = tid >> 5;
    const int lane = tid & 31;
    const int r = lane >> 2;
    const int c = lane & 3;
    const int mi = wid >> 2;
    const int nj = wid & 3;
    const int m0 = blockIdx.x * 128;
    const int z = blockIdx.y;

    const float* Wz = g_wt + (size_t)z * EE * DD;
    float* out = (z == 0) ? g_q : (z == 1) ? g_k : g_v;

    auto load_tile = [&](int st, int k0) {
#pragma unroll
        for (int it = 0; it < 4; ++it) {
            int linear = tid + 256 * it;       // 0..1023
            int m = linear >> 3, g = linear & 7;
            cpa16(&As[st*A_ST + m*AP + 4*g], &g_xt[(size_t)(m0 + m)*EE + k0 + 4*g]);
        }
#pragma unroll
        for (int it = 0; it < 4; ++it) {
            int linear = tid + 256 * it;
            int k = linear >> 5, g = linear & 31;
            cpa16(&Bs[st*B_ST + k*BP + 4*g], &Wz[(size_t)(k0 + k)*DD + 4*g]);
        }
    };

    load_tile(0, 0);  cp_commit();
    load_tile(1, 32); cp_commit();

    float acc[4][4][4];
#pragma unroll
    for (int mt = 0; mt < 4; ++mt)
#pragma unroll
        for (int nt = 0; nt < 4; ++nt)
#pragma unroll
            for (int f = 0; f < 4; ++f) acc[mt][nt][f] = 0.f;

    for (int kt = 0; kt < 32; ++kt) {
        cp_wait<1>();
        __syncthreads();
        if (kt + 2 < 32) load_tile((kt + 2) % 3, 32 * (kt + 2));
        cp_commit();

        const unsigned* A = As + (kt % 3) * A_ST;
        const unsigned* B = Bs + (kt % 3) * B_ST;
#pragma unroll
        for (int kk = 0; kk < 4; ++kk) {
            unsigned a[4][4], b[4][2];
#pragma unroll
            for (int mt = 0; mt < 4; ++mt) {
                int R = 64 * mi + 16 * mt;
                a[mt][0] = A[(R + r) * AP + 8 * kk + c];
                a[mt][1] = A[(R + r + 8) * AP + 8 * kk + c];
                a[mt][2] = A[(R + r) * AP + 8 * kk + c + 4];
                a[mt][3] = A[(R + r + 8) * AP + 8 * kk + c + 4];
            }
#pragma unroll
            for (int nt = 0; nt < 4; ++nt) {
                int N = 32 * nj + 8 * nt;
                b[nt][0] = B[(8 * kk + c) * BP + N + r];
                b[nt][1] = B[(8 * kk + c + 4) * BP + N + r];
            }
#pragma unroll
            for (int mt = 0; mt < 4; ++mt)
#pragma unroll
                for (int nt = 0; nt < 4; ++nt)
                    mma8(acc[mt][nt], a[mt], b[nt]);
        }
    }

    const float mul = (z == 0) ? 0.08838834764831845f : 1.f;  // fold 1/sqrt(D) into q
#pragma unroll
    for (int mt = 0; mt < 4; ++mt) {
        int row0 = m0 + 64 * mi + 16 * mt + r;
#pragma unroll
        for (int nt = 0; nt < 4; ++nt) {
            int col = 32 * nj + 8 * nt + 2 * c;
            *(float2*)&out[(size_t)row0 * DD + col] =
                make_float2(f2tff(acc[mt][nt][0] * mul), f2tff(acc[mt][nt][1] * mul));
            *(float2*)&out[(size_t)(row0 + 8) * DD + col] =
                make_float2(f2tff(acc[mt][nt][2] * mul), f2tff(acc[mt][nt][3] * mul));
        }
    }
}

// ---------------------------------------------------------------------------
// Kernel 2: causal flash attention, tf32 mma, 2-stage cp.async K/V pipeline,
// named pair-barriers for the cross-warp softmax exchange.
// ---------------------------------------------------------------------------
#define KP 132  // K smem stride (== 4 mod 32)
#define VP 136  // V smem stride (== 8 mod 32)
#define PP 132  // P smem stride (also used to stage Q: needs >=128 cols)
#define K_ST (64*KP)
#define V_ST (64*VP)

__global__ __launch_bounds__(256) void attn_kernel(float* __restrict__ out)
{
    extern __shared__ unsigned sm[];
    unsigned* Ks = sm;                       // 2 stages
    unsigned* Vs = sm + 2*K_ST;              // 2 stages
    unsigned* Ps = Vs + 2*V_ST;              // 64*PP (P tile; Q staging in prologue)
    float* smax = (float*)(Ps + 64*PP);      // 128
    float* ssum = smax + 128;                // 128

    const int tid = threadIdx.x;
    const int wid = tid >> 5;
    const int lane = tid & 31;
    const int r = lane >> 2;
    const int c = lane & 3;
    const int mi = wid & 3;
    const int ni = wid >> 2;

    const int bid = blockIdx.x;
    const int qt = (TT / 64 - 1) - (bid >> 3);  // heavy tiles first
    const int b = bid & 7;
    const int t0 = qt * 64;
    const size_t base = (size_t)b * TT;
    const int numTiles = qt + 1;
    const int lr = 16 * mi + r;

    auto load_kv = [&](int st, int s0) {
#pragma unroll
        for (int it = 0; it < 8; ++it) {
            int linear = tid + 256 * it;     // 0..2047
            int row = linear >> 5, g = linear & 31;
            cpa16(&Ks[st*K_ST + row*KP + 4*g], &g_k[(base + s0 + row)*DD + 4*g]);
            cpa16(&Vs[st*V_ST + row*VP + 4*g], &g_v[(base + s0 + row)*DD + 4*g]);
        }
    };

    // Prefetch first two KV tiles immediately.
    load_kv(0, 0);  cp_commit();
    if (numTiles > 1) load_kv(1, 64);
    cp_commit();

    // Stage Q (already scaled + tf32-rounded) through Ps, extract A fragments.
#pragma unroll
    for (int it = 0; it < 8; ++it) {
        int linear = tid + 256 * it;         // 0..2047
        int row = linear >> 5, g = linear & 31;
        *(uint4*)&Ps[row*PP + 4*g] = *(const uint4*)&g_q[(base + t0 + row)*DD + 4*g];
    }
    __syncthreads();

    unsigned qa[16][4];
#pragma unroll
    for (int kc = 0; kc < 16; ++kc) {
        qa[kc][0] = Ps[lr * PP + 8 * kc + c];
        qa[kc][1] = Ps[(lr + 8) * PP + 8 * kc + c];
        qa[kc][2] = Ps[lr * PP + 8 * kc + c + 4];
        qa[kc][3] = Ps[(lr + 8) * PP + 8 * kc + c + 4];
    }

    float oacc[8][4];
#pragma unroll
    for (int nt = 0; nt < 8; ++nt)
#pragma unroll
        for (int f = 0; f < 4; ++f) oacc[nt][f] = 0.f;
    float m_run[2] = {-INFINITY, -INFINITY};
    float l_run[2] = {0.f, 0.f};

    for (int ti = 0; ti < numTiles; ++ti) {
        cp_wait<1>();
        __syncthreads();   // KV tile ti ready; also fences Ps/prev-tile reads

        const unsigned* Kc = Ks + (ti & 1) * K_ST;
        const unsigned* Vc = Vs + (ti & 1) * V_ST;

        // ---- S = (Q*scale) K^T : warp computes 16 rows x 32 cols ----
        float sacc[4][4];
#pragma unroll
        for (int nt = 0; nt < 4; ++nt)
#pragma unroll
            for (int f = 0; f < 4; ++f) sacc[nt][f] = 0.f;

#pragma unroll
        for (int kc = 0; kc < 16; ++kc) {
            unsigned kb[4][2];
#pragma unroll
            for (int nt = 0; nt < 4; ++nt) {
                int n = 32 * ni + 8 * nt + r;
                kb[nt][0] = Kc[n * KP + 8 * kc + c];
                kb[nt][1] = Kc[n * KP + 8 * kc + c + 4];
            }
#pragma unroll
            for (int nt = 0; nt < 4; ++nt)
                mma8(sacc[nt], qa[kc], kb[nt]);
        }

        // ---- causal mask (diagonal tile only) ----
        if (ti == numTiles - 1) {
#pragma unroll
            for (int nt = 0; nt < 4; ++nt)
#pragma unroll
                for (int f = 0; f < 4; ++f) {
                    int row = lr + ((f >= 2) ? 8 : 0);
                    int col = 32 * ni + 8 * nt + 2 * c + (f & 1);
                    if (col > row) sacc[nt][f] = -1e30f;
                }
        }

        // ---- partial row max, exchange within 2-warp pair ----
        float pmax[2];
#pragma unroll
        for (int h = 0; h < 2; ++h) {
            float mx = -INFINITY;
#pragma unroll
            for (int nt = 0; nt < 4; ++nt) {
                mx = fmaxf(mx, sacc[nt][2 * h]);
                mx = fmaxf(mx, sacc[nt][2 * h + 1]);
            }
            mx = fmaxf(mx, __shfl_xor_sync(0xffffffffu, mx, 1));
            mx = fmaxf(mx, __shfl_xor_sync(0xffffffffu, mx, 2));
            pmax[h] = mx;
        }
        if (c == 0) {
            smax[ni * 64 + lr] = pmax[0];
            smax[ni * 64 + lr + 8] = pmax[1];
        }
        asm volatile("bar.sync %0, 64;" :: "r"(1 + mi));

        float m_new[2], alpha[2];
#pragma unroll
        for (int h = 0; h < 2; ++h) {
            float mt_ = fmaxf(smax[lr + 8 * h], smax[64 + lr + 8 * h]);
            m_new[h] = fmaxf(m_run[h], mt_);
            alpha[h] = __expf(m_run[h] - m_new[h]);
            m_run[h] = m_new[h];
        }

        // ---- exp, write P (tf32), partial row sum ----
#pragma unroll
        for (int h = 0; h < 2; ++h) {
            float s_ = 0.f;
#pragma unroll
            for (int nt = 0; nt < 4; ++nt) {
                float p0 = __expf(sacc[nt][2 * h] - m_new[h]);
                float p1 = __expf(sacc[nt][2 * h + 1] - m_new[h]);
                s_ += p0 + p1;
                *(uint2*)&Ps[(lr + 8 * h) * PP + 32 * ni + 8 * nt + 2 * c] =
                    make_uint2(f2tf(p0), f2tf(p1));
            }
            s_ += __shfl_xor_sync(0xffffffffu, s_, 1);
            s_ += __shfl_xor_sync(0xffffffffu, s_, 2);
            if (c == 0) ssum[ni * 64 + lr + 8 * h] = s_;
        }
        asm volatile("bar.sync %0, 64;" :: "r"(1 + mi));

#pragma unroll
        for (int h = 0; h < 2; ++h)
            l_run[h] = l_run[h] * alpha[h] + ssum[lr + 8 * h] + ssum[64 + lr + 8 * h];

        // ---- rescale O ----
#pragma unroll
        for (int nt = 0; nt < 8; ++nt) {
            oacc[nt][0] *= alpha[0];
            oacc[nt][1] *= alpha[0];
            oacc[nt][2] *= alpha[1];
            oacc[nt][3] *= alpha[1];
        }

        // ---- O += P V : warp computes 16 rows x 64 cols (n half = ni) ----
#pragma unroll
        for (int kc2 = 0; kc2 < 8; ++kc2) {
            unsigned pa[4];
            pa[0] = Ps[lr * PP + 8 * kc2 + c];
            pa[1] = Ps[(lr + 8) * PP + 8 * kc2 + c];
            pa[2] = Ps[lr * PP + 8 * kc2 + c + 4];
            pa[3] = Ps[(lr + 8) * PP + 8 * kc2 + c + 4];
#pragma unroll
            for (int nt = 0; nt < 8; ++nt) {
                unsigned vb[2];
                int n = 64 * ni + 8 * nt + r;
                vb[0] = Vc[(8 * kc2 + c) * VP + n];
                vb[1] = Vc[(8 * kc2 + c + 4) * VP + n];
                mma8(oacc[nt], pa, vb);
            }
        }

        __syncthreads();   // all reads of this stage done -> safe to prefetch into it
        if (ti + 2 < numTiles) load_kv(ti & 1, 64 * (ti + 2));
        cp_commit();       // always commit to keep group accounting aligned
    }

    // ---- epilogue ----
    float inv0 = 1.f / l_run[0];
    float inv1 = 1.f / l_run[1];
#pragma unroll
    for (int nt = 0; nt < 8; ++nt) {
        int col = 64 * ni + 8 * nt + 2 * c;
        size_t row0 = base + t0 + lr;
        *(float2*)&out[row0 * DD + col] =
            make_float2(oacc[nt][0] * inv0, oacc[nt][1] * inv0);
        *(float2*)&out[(row0 + 8) * DD + col] =
            make_float2(oacc[nt][2] * inv1, oacc[nt][3] * inv1);
    }
}

// ---------------------------------------------------------------------------
extern "C" void kernel_launch(void* const* d_in, const int* in_sizes, int n_in,
                              void* d_out, int out_size)
{
    (void)in_sizes; (void)n_in; (void)out_size;
    const float* x  = (const float*)d_in[0];
    const float* Wk = (const float*)d_in[1];
    const float* Wq = (const float*)d_in[2];
    const float* Wv = (const float*)d_in[3];
    float* out = (float*)d_out;

    const int NX = BT*EE/4, NW = EE*DD/4;
    const int nCvt = (NX + 3*NW + 255) / 256;
    cvt_kernel<<<nCvt, 256>>>(x, Wk, Wq, Wv);

    const int proj_smem = (3*A_ST + 3*B_ST) * 4;      // 107,520 B
    cudaFuncSetAttribute(proj_kernel,
                         cudaFuncAttributeMaxDynamicSharedMemorySize, proj_smem);
    dim3 pgrid(BT / 128, 3);
    proj_kernel<<<pgrid, 256, proj_smem>>>();

    const int attn_smem = (2*K_ST + 2*V_ST + 64*PP + 256) * 4;  // 172,032 B
    cudaFuncSetAttribute(attn_kernel,
                         cudaFuncAttributeMaxDynamicSharedMemorySize, attn_smem);
    attn_kernel<<<TT / 64 * BB, 256, attn_smem>>>(out);
}

// round 4
// speedup vs baseline: 4.1002x; 1.0265x over previous
#include <cuda_runtime.h>
#include <math.h>

#define BB 8
#define TT 2048
#define EE 1024
#define DD 128
#define BT (BB*TT)

// Device scratch (no allocations allowed)
__device__ float g_xt[BT*EE];      // x rounded to tf32
__device__ float g_wt[3*EE*DD];    // Wq,Wk,Wv rounded to tf32
__device__ float g_q[BT*DD];       // q*scale, tf32-rounded
__device__ float g_k[BT*DD];
__device__ float g_v[BT*DD];

__device__ __forceinline__ unsigned f2tf(float x) {
    unsigned u;
    asm("cvt.rna.tf32.f32 %0, %1;" : "=r"(u) : "f"(x));
    return u;
}
__device__ __forceinline__ float f2tff(float x) { return __uint_as_float(f2tf(x)); }

__device__ __forceinline__ void cpa16(unsigned* dst, const void* src) {
    unsigned d = (unsigned)__cvta_generic_to_shared(dst);
    asm volatile("cp.async.cg.shared.global [%0], [%1], 16;\n" :: "r"(d), "l"(src));
}
__device__ __forceinline__ void cp_commit() { asm volatile("cp.async.commit_group;\n"); }
template<int N> __device__ __forceinline__ void cp_wait() {
    asm volatile("cp.async.wait_group %0;\n" :: "n"(N));
}

__device__ __forceinline__ void mma8(float* d, const unsigned* a, const unsigned* b) {
    asm volatile(
        "mma.sync.aligned.m16n8k8.row.col.f32.tf32.tf32.f32 "
        "{%0,%1,%2,%3}, {%4,%5,%6,%7}, {%8,%9}, {%0,%1,%2,%3};\n"
        : "+f"(d[0]), "+f"(d[1]), "+f"(d[2]), "+f"(d[3])
        : "r"(a[0]), "r"(a[1]), "r"(a[2]), "r"(a[3]), "r"(b[0]), "r"(b[1]));
}

// ---------------------------------------------------------------------------
// Kernel 0: elementwise tf32 pre-round of x and the three W matrices.
// ---------------------------------------------------------------------------
__global__ __launch_bounds__(256) void cvt_kernel(const float* __restrict__ x,
                                                  const float* __restrict__ Wk,
                                                  const float* __restrict__ Wq,
                                                  const float* __restrict__ Wv)
{
    const int NX = BT*EE/4;
    const int NW = EE*DD/4;
    int i = blockIdx.x * 256 + threadIdx.x;
    if (i < NX) {
        float4 v = ((const float4*)x)[i];
        ((float4*)g_xt)[i] = make_float4(f2tff(v.x), f2tff(v.y), f2tff(v.z), f2tff(v.w));
    } else {
        int j = i - NX;
        if (j < 3*NW) {
            int z = j / NW, p = j - z*NW;
            const float4* src = (const float4*)((z == 0) ? Wq : (z == 1) ? Wk : Wv);
            float4 v = src[p];
            ((float4*)g_wt)[z*NW + p] =
                make_float4(f2tff(v.x), f2tff(v.y), f2tff(v.z), f2tff(v.w));
        }
    }
}

// ---------------------------------------------------------------------------
// Kernel 1: QKV projection, tf32 mma, 3-stage cp.async pipeline, 2 CTAs/SM.
// Block tile 128x128, 8 warps (2m x 4n), warp tile 64x32, BK=32.
// ---------------------------------------------------------------------------
#define AP 36   // A smem stride (== 4 mod 32)
#define BP 136  // B smem stride (== 8 mod 32)
#define A_ST (128*AP)
#define B_ST (32*BP)

__global__ __launch_bounds__(256, 2) void proj_kernel()
{
    extern __shared__ unsigned psm[];
    unsigned* As = psm;
    unsigned* Bs = psm + 3*A_ST;

    const int tid = threadIdx.x;
    const int wid = tid >> 5;
    const int lane = tid & 31;
    const int r = lane >> 2;
    const int c = lane & 3;
    const int mi = wid >> 2;
    const int nj = wid & 3;
    const int m0 = blockIdx.x * 128;
    const int z = blockIdx.y;

    const float* Wz = g_wt + (size_t)z * EE * DD;
    float* out = (z == 0) ? g_q : (z == 1) ? g_k : g_v;

    auto load_tile = [&](int st, int k0) {
#pragma unroll
        for (int it = 0; it < 4; ++it) {
            int linear = tid + 256 * it;
            int m = linear >> 3, g = linear & 7;
            cpa16(&As[st*A_ST + m*AP + 4*g], &g_xt[(size_t)(m0 + m)*EE + k0 + 4*g]);
        }
#pragma unroll
        for (int it = 0; it < 4; ++it) {
            int linear = tid + 256 * it;
            int k = linear >> 5, g = linear & 31;
            cpa16(&Bs[st*B_ST + k*BP + 4*g], &Wz[(size_t)(k0 + k)*DD + 4*g]);
        }
    };

    load_tile(0, 0);  cp_commit();
    load_tile(1, 32); cp_commit();

    float acc[4][4][4];
#pragma unroll
    for (int mt = 0; mt < 4; ++mt)
#pragma unroll
        for (int nt = 0; nt < 4; ++nt)
#pragma unroll
            for (int f = 0; f < 4; ++f) acc[mt][nt][f] = 0.f;

    for (int kt = 0; kt < 32; ++kt) {
        cp_wait<1>();
        __syncthreads();
        if (kt + 2 < 32) load_tile((kt + 2) % 3, 32 * (kt + 2));
        cp_commit();

        const unsigned* A = As + (kt % 3) * A_ST;
        const unsigned* B = Bs + (kt % 3) * B_ST;
#pragma unroll
        for (int kk = 0; kk < 4; ++kk) {
            unsigned a[4][4], b[4][2];
#pragma unroll
            for (int mt = 0; mt < 4; ++mt) {
                int R = 64 * mi + 16 * mt;
                a[mt][0] = A[(R + r) * AP + 8 * kk + c];
                a[mt][1] = A[(R + r + 8) * AP + 8 * kk + c];
                a[mt][2] = A[(R + r) * AP + 8 * kk + c + 4];
                a[mt][3] = A[(R + r + 8) * AP + 8 * kk + c + 4];
            }
#pragma unroll
            for (int nt = 0; nt < 4; ++nt) {
                int N = 32 * nj + 8 * nt;
                b[nt][0] = B[(8 * kk + c) * BP + N + r];
                b[nt][1] = B[(8 * kk + c + 4) * BP + N + r];
            }
#pragma unroll
            for (int mt = 0; mt < 4; ++mt)
#pragma unroll
                for (int nt = 0; nt < 4; ++nt)
                    mma8(acc[mt][nt], a[mt], b[nt]);
        }
    }

    const float mul = (z == 0) ? 0.08838834764831845f : 1.f;  // fold 1/sqrt(D) into q
#pragma unroll
    for (int mt = 0; mt < 4; ++mt) {
        int row0 = m0 + 64 * mi + 16 * mt + r;
#pragma unroll
        for (int nt = 0; nt < 4; ++nt) {
            int col = 32 * nj + 8 * nt + 2 * c;
            *(float2*)&out[(size_t)row0 * DD + col] =
                make_float2(f2tff(acc[mt][nt][0] * mul), f2tff(acc[mt][nt][1] * mul));
            *(float2*)&out[(size_t)(row0 + 8) * DD + col] =
                make_float2(f2tff(acc[mt][nt][2] * mul), f2tff(acc[mt][nt][3] * mul));
        }
    }
}

// ---------------------------------------------------------------------------
// Kernel 2: causal flash attention, tf32 mma, 3-stage cp.async KV pipeline,
// ONE __syncthreads + ONE named pair-barrier per tile, partial-l epilogue.
// ---------------------------------------------------------------------------
#define KP 132  // K smem stride (== 4 mod 32)
#define VP 136  // V smem stride (== 8 mod 32)
#define PP 68   // P smem stride (== 4 mod 32), 64-wide P tile
#define K_ST (64*KP)
#define V_ST (64*VP)
#define STG  (K_ST + V_ST)

__global__ __launch_bounds__(256) void attn_kernel(float* __restrict__ out)
{
    extern __shared__ unsigned sm[];
    unsigned* Ps = sm + 3*STG;               // 64*PP
    float* smax = (float*)(Ps + 64*PP);      // 128
    float* ssum = smax + 128;                // 128

    const int tid = threadIdx.x;
    const int wid = tid >> 5;
    const int lane = tid & 31;
    const int r = lane >> 2;
    const int c = lane & 3;
    const int mi = wid & 3;
    const int ni = wid >> 2;

    const int bid = blockIdx.x;
    const int qt = (TT / 64 - 1) - (bid >> 3);  // heavy tiles first
    const int b = bid & 7;
    const int t0 = qt * 64;
    const size_t base = (size_t)b * TT;
    const int numTiles = qt + 1;
    const int lr = 16 * mi + r;

    auto load_kv = [&](int st, int s0) {
        unsigned* Kd = sm + st * STG;
        unsigned* Vd = Kd + K_ST;
#pragma unroll
        for (int it = 0; it < 8; ++it) {
            int linear = tid + 256 * it;
            int row = linear >> 5, g = linear & 31;
            cpa16(&Kd[row*KP + 4*g], &g_k[(base + s0 + row)*DD + 4*g]);
            cpa16(&Vd[row*VP + 4*g], &g_v[(base + s0 + row)*DD + 4*g]);
        }
    };

    // Prefetch first two KV tiles.
    load_kv(0, 0);  cp_commit();
    if (numTiles > 1) load_kv(1, 64);
    cp_commit();

    // Stage Q in two 64-col passes through Ps, extract A fragments.
    unsigned qa[16][4];
#pragma unroll
    for (int p = 0; p < 2; ++p) {
#pragma unroll
        for (int it = 0; it < 4; ++it) {
            int linear = tid + 256 * it;       // 0..1023
            int row = linear >> 4, g = linear & 15;
            *(uint4*)&Ps[row*PP + 4*g] =
                *(const uint4*)&g_q[(base + t0 + row)*DD + 64*p + 4*g];
        }
        __syncthreads();
#pragma unroll
        for (int kc = 0; kc < 8; ++kc) {
            qa[8*p + kc][0] = Ps[lr * PP + 8 * kc + c];
            qa[8*p + kc][1] = Ps[(lr + 8) * PP + 8 * kc + c];
            qa[8*p + kc][2] = Ps[lr * PP + 8 * kc + c + 4];
            qa[8*p + kc][3] = Ps[(lr + 8) * PP + 8 * kc + c + 4];
        }
        __syncthreads();
    }

    float oacc[8][4];
#pragma unroll
    for (int nt = 0; nt < 8; ++nt)
#pragma unroll
        for (int f = 0; f < 4; ++f) oacc[nt][f] = 0.f;
    float m_run[2] = {-INFINITY, -INFINITY};
    float l_part[2] = {0.f, 0.f};            // own 32-col half only

    for (int ti = 0; ti < numTiles; ++ti) {
        cp_wait<1>();
        __syncthreads();   // tile ti ready; all warps done with iter ti-1
        if (ti + 2 < numTiles) load_kv((ti + 2) % 3, 64 * (ti + 2));
        cp_commit();

        const unsigned* Kc = sm + (ti % 3) * STG;
        const unsigned* Vc = Kc + K_ST;

        // ---- S = (Q*scale) K^T : warp computes 16 rows x 32 cols ----
        float sacc[4][4];
#pragma unroll
        for (int nt = 0; nt < 4; ++nt)
#pragma unroll
            for (int f = 0; f < 4; ++f) sacc[nt][f] = 0.f;

#pragma unroll
        for (int kc = 0; kc < 16; ++kc) {
            unsigned kb[4][2];
#pragma unroll
            for (int nt = 0; nt < 4; ++nt) {
                int n = 32 * ni + 8 * nt + r;
                kb[nt][0] = Kc[n * KP + 8 * kc + c];
                kb[nt][1] = Kc[n * KP + 8 * kc + c + 4];
            }
#pragma unroll
            for (int nt = 0; nt < 4; ++nt)
                mma8(sacc[nt], qa[kc], kb[nt]);
        }

        // ---- causal mask (diagonal tile only) ----
        if (ti == numTiles - 1) {
#pragma unroll
            for (int nt = 0; nt < 4; ++nt)
#pragma unroll
                for (int f = 0; f < 4; ++f) {
                    int row = lr + ((f >= 2) ? 8 : 0);
                    int col = 32 * ni + 8 * nt + 2 * c + (f & 1);
                    if (col > row) sacc[nt][f] = -1e30f;
                }
        }

        // ---- partial row max, exchange within 2-warp pair ----
        float pmax[2];
#pragma unroll
        for (int h = 0; h < 2; ++h) {
            float mx = -INFINITY;
#pragma unroll
            for (int nt = 0; nt < 4; ++nt) {
                mx = fmaxf(mx, sacc[nt][2 * h]);
                mx = fmaxf(mx, sacc[nt][2 * h + 1]);
            }
            mx = fmaxf(mx, __shfl_xor_sync(0xffffffffu, mx, 1));
            mx = fmaxf(mx, __shfl_xor_sync(0xffffffffu, mx, 2));
            pmax[h] = mx;
        }
        if (c == 0) {
            smax[ni * 64 + lr] = pmax[0];
            smax[ni * 64 + lr + 8] = pmax[1];
        }
        asm volatile("bar.sync %0, 64;" :: "r"(1 + mi));

        float m_new[2], alpha[2];
#pragma unroll
        for (int h = 0; h < 2; ++h) {
            float mt_ = fmaxf(smax[lr + 8 * h], smax[64 + lr + 8 * h]);
            m_new[h] = fmaxf(m_run[h], mt_);
            alpha[h] = __expf(m_run[h] - m_new[h]);
            m_run[h] = m_new[h];
        }

        // ---- exp, write P (tf32), accumulate OWN-half row sum ----
#pragma unroll
        for (int h = 0; h < 2; ++h) {
            float s_ = 0.f;
#pragma unroll
            for (int nt = 0; nt < 4; ++nt) {
                float p0 = __expf(sacc[nt][2 * h] - m_new[h]);
                float p1 = __expf(sacc[nt][2 * h + 1] - m_new[h]);
                s_ += p0 + p1;
                *(uint2*)&Ps[(lr + 8 * h) * PP + 32 * ni + 8 * nt + 2 * c] =
                    make_uint2(f2tf(p0), f2tf(p1));
            }
            s_ += __shfl_xor_sync(0xffffffffu, s_, 1);
            s_ += __shfl_xor_sync(0xffffffffu, s_, 2);
            l_part[h] = l_part[h] * alpha[h] + s_;
        }

        // ---- rescale O ----
#pragma unroll
        for (int nt = 0; nt < 8; ++nt) {
            oacc[nt][0] *= alpha[0];
            oacc[nt][1] *= alpha[0];
            oacc[nt][2] *= alpha[1];
            oacc[nt][3] *= alpha[1];
        }

        // P written by this pair; O phase reads it. The pair-barrier above
        // (next tile) orders the next overwrite; V reads fenced by top sync.
        asm volatile("bar.sync %0, 64;" :: "r"(1 + mi));

        // ---- O += P V : warp computes 16 rows x 64 cols (n half = ni) ----
#pragma unroll
        for (int kc2 = 0; kc2 < 8; ++kc2) {
            unsigned pa[4];
            pa[0] = Ps[lr * PP + 8 * kc2 + c];
            pa[1] = Ps[(lr + 8) * PP + 8 * kc2 + c];
            pa[2] = Ps[lr * PP + 8 * kc2 + c + 4];
            pa[3] = Ps[(lr + 8) * PP + 8 * kc2 + c + 4];
#pragma unroll
            for (int nt = 0; nt < 8; ++nt) {
                unsigned vb[2];
                int n = 64 * ni + 8 * nt + r;
                vb[0] = Vc[(8 * kc2 + c) * VP + n];
                vb[1] = Vc[(8 * kc2 + c + 4) * VP + n];
                mma8(oacc[nt], pa, vb);
            }
        }
    }

    // ---- epilogue: combine the two l halves once, normalize, store ----
    if (c == 0) {
        ssum[ni * 64 + lr] = l_part[0];
        ssum[ni * 64 + lr + 8] = l_part[1];
    }
    asm volatile("bar.sync %0, 64;" :: "r"(1 + mi));
    float inv0 = 1.f / (l_part[0] + ssum[(1 - ni) * 64 + lr]);
    float inv1 = 1.f / (l_part[1] + ssum[(1 - ni) * 64 + lr + 8]);

#pragma unroll
    for (int nt = 0; nt < 8; ++nt) {
        int col = 64 * ni + 8 * nt + 2 * c;
        size_t row0 = base + t0 + lr;
        *(float2*)&out[row0 * DD + col] =
            make_float2(oacc[nt][0] * inv0, oacc[nt][1] * inv0);
        *(float2*)&out[(row0 + 8) * DD + col] =
            make_float2(oacc[nt][2] * inv1, oacc[nt][3] * inv1);
    }
}

// ---------------------------------------------------------------------------
extern "C" void kernel_launch(void* const* d_in, const int* in_sizes, int n_in,
                              void* d_out, int out_size)
{
    (void)in_sizes; (void)n_in; (void)out_size;
    const float* x  = (const float*)d_in[0];
    const float* Wk = (const float*)d_in[1];
    const float* Wq = (const float*)d_in[2];
    const float* Wv = (const float*)d_in[3];
    float* out = (float*)d_out;

    const int NX = BT*EE/4, NW = EE*DD/4;
    const int nCvt = (NX + 3*NW + 255) / 256;
    cvt_kernel<<<nCvt, 256>>>(x, Wk, Wq, Wv);

    const int proj_smem = (3*A_ST + 3*B_ST) * 4;
    cudaFuncSetAttribute(proj_kernel,
                         cudaFuncAttributeMaxDynamicSharedMemorySize, proj_smem);
    dim3 pgrid(BT / 128, 3);
    proj_kernel<<<pgrid, 256, proj_smem>>>();

    const int attn_smem = (3*STG + 64*PP + 256) * 4;   // ~224 KB
    cudaFuncSetAttribute(attn_kernel,
                         cudaFuncAttributeMaxDynamicSharedMemorySize, attn_smem);
    attn_kernel<<<TT / 64 * BB, 256, attn_smem>>>(out);
}

// round 6
// speedup vs baseline: 4.1382x; 1.0093x over previous
#include <cuda_runtime.h>
#include <math.h>

#define BB 8
#define TT 2048
#define EE 1024
#define DD 128
#define BT (BB*TT)

// Device scratch (no allocations allowed)
__device__ float g_xt[BT*EE];      // x rounded to tf32
__device__ float g_wt[3*EE*DD];    // W^T per z: [n][k], tf32-rounded
__device__ float g_q[BT*DD];       // q*scale, tf32-rounded
__device__ float g_k[BT*DD];       // tf32-rounded
__device__ float g_vT[BT*DD];      // V transposed per batch: [b][d][s], tf32

__device__ __forceinline__ unsigned f2tf(float x) {
    unsigned u;
    asm("cvt.rna.tf32.f32 %0, %1;" : "=r"(u) : "f"(x));
    return u;
}
__device__ __forceinline__ float f2tff(float x) { return __uint_as_float(f2tf(x)); }

__device__ __forceinline__ void cpa16(unsigned* dst, const void* src) {
    unsigned d = (unsigned)__cvta_generic_to_shared(dst);
    asm volatile("cp.async.cg.shared.global [%0], [%1], 16;\n" :: "r"(d), "l"(src));
}
__device__ __forceinline__ void cp_commit() { asm volatile("cp.async.commit_group;\n"); }
template<int N> __device__ __forceinline__ void cp_wait() {
    asm volatile("cp.async.wait_group %0;\n" :: "n"(N));
}

__device__ __forceinline__ void mma8(float* d, const unsigned* a, const unsigned* b) {
    asm volatile(
        "mma.sync.aligned.m16n8k8.row.col.f32.tf32.tf32.f32 "
        "{%0,%1,%2,%3}, {%4,%5,%6,%7}, {%8,%9}, {%0,%1,%2,%3};\n"
        : "+f"(d[0]), "+f"(d[1]), "+f"(d[2]), "+f"(d[3])
        : "r"(a[0]), "r"(a[1]), "r"(a[2]), "r"(a[3]), "r"(b[0]), "r"(b[1]));
}

// ldmatrix x4: four 8x8-b16 (== 8x4-b32) tiles; each lane passes its row addr.
__device__ __forceinline__ void ldm4(unsigned& r0, unsigned& r1, unsigned& r2,
                                     unsigned& r3, const unsigned* p) {
    unsigned a = (unsigned)__cvta_generic_to_shared(p);
    asm volatile("ldmatrix.sync.aligned.m8n8.x4.shared.b16 {%0,%1,%2,%3}, [%4];"
                 : "=r"(r0), "=r"(r1), "=r"(r2), "=r"(r3) : "r"(a));
}

// ---------------------------------------------------------------------------
// Kernel 0: tf32 pre-round of x; W rounded AND transposed to [n][k].
// ---------------------------------------------------------------------------
__global__ __launch_bounds__(256) void cvt_kernel(const float* __restrict__ x,
                                                  const float* __restrict__ Wk,
                                                  const float* __restrict__ Wq,
                                                  const float* __restrict__ Wv)
{
    const int NX = BT*EE/4;
    const int NW = EE*DD/4;
    int i = blockIdx.x * 256 + threadIdx.x;
    if (i < NX) {
        float4 v = ((const float4*)x)[i];
        ((float4*)g_xt)[i] = make_float4(f2tff(v.x), f2tff(v.y), f2tff(v.z), f2tff(v.w));
    } else {
        int j = i - NX;
        if (j < 3*NW) {
            int z = j / NW, p = j - z*NW;
            const float4* src = (const float4*)((z == 0) ? Wq : (z == 1) ? Wk : Wv);
            float4 v = src[p];                 // W[k][4nq..4nq+3]
            int k = p >> 5;                    // DD/4 == 32
            int nq = p & 31;
            float* dst = g_wt + (size_t)z * EE * DD;
            dst[(size_t)(4*nq + 0)*EE + k] = f2tff(v.x);
            dst[(size_t)(4*nq + 1)*EE + k] = f2tff(v.y);
            dst[(size_t)(4*nq + 2)*EE + k] = f2tff(v.z);
            dst[(size_t)(4*nq + 3)*EE + k] = f2tff(v.w);
        }
    }
}

// ---------------------------------------------------------------------------
// Kernel 1: QKV projection, tf32 mma + ldmatrix fragments, 3-stage cp.async.
// Block tile 128x128, 8 warps (2m x 4n), warp tile 64x32, BK=32.
// A smem [m=128][k=32] stride 36; B smem (W^T) [n=128][k=32] stride 36.
// ---------------------------------------------------------------------------
#define AP 36
#define BP2 36
#define A_ST (128*AP)
#define B_ST (128*BP2)

__global__ __launch_bounds__(256, 2) void proj_kernel()
{
    extern __shared__ unsigned psm[];
    unsigned* As = psm;
    unsigned* Bs = psm + 3*A_ST;

    const int tid = threadIdx.x;
    const int wid = tid >> 5;
    const int lane = tid & 31;
    const int r = lane >> 2;
    const int c = lane & 3;
    const int g8 = lane >> 3;     // ldmatrix lane group 0..3
    const int rw = lane & 7;      // row within group
    const int mi = wid >> 2;
    const int nj = wid & 3;
    const int m0 = blockIdx.x * 128;
    const int z = blockIdx.y;

    const float* Wz = g_wt + (size_t)z * EE * DD;   // [n][k]

    auto load_tile = [&](int st, int k0) {
#pragma unroll
        for (int it = 0; it < 4; ++it) {
            int linear = tid + 256 * it;       // 0..1023
            int m = linear >> 3, g = linear & 7;
            cpa16(&As[st*A_ST + m*AP + 4*g], &g_xt[(size_t)(m0 + m)*EE + k0 + 4*g]);
        }
#pragma unroll
        for (int it = 0; it < 4; ++it) {
            int linear = tid + 256 * it;
            int n = linear >> 3, g = linear & 7;
            cpa16(&Bs[st*B_ST + n*BP2 + 4*g], &Wz[(size_t)n*EE + k0 + 4*g]);
        }
    };

    load_tile(0, 0);  cp_commit();
    load_tile(1, 32); cp_commit();

    float acc[4][4][4];
#pragma unroll
    for (int mt = 0; mt < 4; ++mt)
#pragma unroll
        for (int nt = 0; nt < 4; ++nt)
#pragma unroll
            for (int f = 0; f < 4; ++f) acc[mt][nt][f] = 0.f;

    // ldmatrix lane base offsets (relative to stage base)
    const int aoff = (64*mi + (g8 & 1)*8 + rw)*AP + (g8 >> 1)*4;
    const int boff = (32*nj + 8*(g8 >> 1) + rw)*BP2 + 4*(g8 & 1);

    for (int kt = 0; kt < 32; ++kt) {
        cp_wait<1>();
        __syncthreads();
        if (kt + 2 < 32) load_tile((kt + 2) % 3, 32 * (kt + 2));
        cp_commit();

        const unsigned* A = As + (kt % 3) * A_ST;
        const unsigned* B = Bs + (kt % 3) * B_ST;
#pragma unroll
        for (int kk = 0; kk < 4; ++kk) {
            unsigned a[4][4], b[4][2];
#pragma unroll
            for (int mt = 0; mt < 4; ++mt)
                ldm4(a[mt][0], a[mt][1], a[mt][2], a[mt][3],
                     A + aoff + mt*16*AP + 8*kk);
            ldm4(b[0][0], b[0][1], b[1][0], b[1][1], B + boff + 8*kk);
            ldm4(b[2][0], b[2][1], b[3][0], b[3][1], B + boff + 16*BP2 + 8*kk);
#pragma unroll
            for (int mt = 0; mt < 4; ++mt)
#pragma unroll
                for (int nt = 0; nt < 4; ++nt)
                    mma8(acc[mt][nt], a[mt], b[nt]);
        }
    }

    if (z == 2) {
        // write V transposed: g_vT[b][d][t]
#pragma unroll
        for (int mt = 0; mt < 4; ++mt) {
            int row0 = m0 + 64 * mi + 16 * mt + r;
            float* vt = g_vT + (size_t)(row0 >> 11) * DD * TT;
            int t = row0 & (TT - 1);
#pragma unroll
            for (int nt = 0; nt < 4; ++nt) {
                int col = 32 * nj + 8 * nt + 2 * c;
                vt[(size_t)col * TT + t]           = f2tff(acc[mt][nt][0]);
                vt[(size_t)(col + 1) * TT + t]     = f2tff(acc[mt][nt][1]);
                vt[(size_t)col * TT + t + 8]       = f2tff(acc[mt][nt][2]);
                vt[(size_t)(col + 1) * TT + t + 8] = f2tff(acc[mt][nt][3]);
            }
        }
    } else {
        float* out = (z == 0) ? g_q : g_k;
        const float mul = (z == 0) ? 0.08838834764831845f : 1.f;
#pragma unroll
        for (int mt = 0; mt < 4; ++mt) {
            int row0 = m0 + 64 * mi + 16 * mt + r;
#pragma unroll
            for (int nt = 0; nt < 4; ++nt) {
                int col = 32 * nj + 8 * nt + 2 * c;
                *(float2*)&out[(size_t)row0 * DD + col] =
                    make_float2(f2tff(acc[mt][nt][0]*mul), f2tff(acc[mt][nt][1]*mul));
                *(float2*)&out[(size_t)(row0 + 8) * DD + col] =
                    make_float2(f2tff(acc[mt][nt][2]*mul), f2tff(acc[mt][nt][3]*mul));
            }
        }
    }
}

// ---------------------------------------------------------------------------
// Kernel 2: causal flash attention, tf32 mma, ldmatrix fragments,
// 3-stage cp.async pipeline (K n-major, V^T d-major), partial-l epilogue.
// ---------------------------------------------------------------------------
#define KP 132   // K smem stride (n-major rows), ==4 mod 32
#define VTP 68   // V^T smem stride (d-major rows), ==4 mod 32
#define PP 68    // P smem stride
#define K_ST (64*KP)
#define VT_ST (128*VTP)
#define STG  (K_ST + VT_ST)

__global__ __launch_bounds__(256) void attn_kernel(float* __restrict__ out)
{
    extern __shared__ unsigned sm[];
    unsigned* Ps = sm + 3*STG;               // 64*PP
    float* smax = (float*)(Ps + 64*PP);      // 128
    float* ssum = smax + 128;                // 128

    const int tid = threadIdx.x;
    const int wid = tid >> 5;
    const int lane = tid & 31;
    const int r = lane >> 2;
    const int c = lane & 3;
    const int g8 = lane >> 3;
    const int rw = lane & 7;
    const int mi = wid & 3;
    const int ni = wid >> 2;

    const int bid = blockIdx.x;
    const int qt = (TT / 64 - 1) - (bid >> 3);  // heavy tiles first
    const int b = bid & 7;
    const int t0 = qt * 64;
    const size_t base = (size_t)b * TT;
    const int numTiles = qt + 1;
    const int lr = 16 * mi + r;

    auto load_kv = [&](int st, int s0) {
        unsigned* Kd = sm + st * STG;
        unsigned* Vd = Kd + K_ST;
#pragma unroll
        for (int it = 0; it < 8; ++it) {
            int linear = tid + 256 * it;         // K: 64 rows x 32 f4
            int row = linear >> 5, g = linear & 31;
            cpa16(&Kd[row*KP + 4*g], &g_k[(base + s0 + row)*DD + 4*g]);
        }
#pragma unroll
        for (int it = 0; it < 8; ++it) {
            int linear = tid + 256 * it;         // VT: 128 rows x 16 f4
            int row = linear >> 4, g = linear & 15;
            cpa16(&Vd[row*VTP + 4*g],
                  &g_vT[((size_t)b*DD + row)*TT + s0 + 4*g]);
        }
    };

    load_kv(0, 0);  cp_commit();
    if (numTiles > 1) load_kv(1, 64);
    cp_commit();

    // Stage Q in two 64-col passes through Ps, extract A fragments (scalar: cold).
    unsigned qa[16][4];
#pragma unroll
    for (int p = 0; p < 2; ++p) {
#pragma unroll
        for (int it = 0; it < 4; ++it) {
            int linear = tid + 256 * it;
            int row = linear >> 4, g = linear & 15;
            *(uint4*)&Ps[row*PP + 4*g] =
                *(const uint4*)&g_q[(base + t0 + row)*DD + 64*p + 4*g];
        }
        __syncthreads();
#pragma unroll
        for (int kc = 0; kc < 8; ++kc) {
            qa[8*p + kc][0] = Ps[lr * PP + 8 * kc + c];
            qa[8*p + kc][1] = Ps[(lr + 8) * PP + 8 * kc + c];
            qa[8*p + kc][2] = Ps[lr * PP + 8 * kc + c + 4];
            qa[8*p + kc][3] = Ps[(lr + 8) * PP + 8 * kc + c + 4];
        }
        __syncthreads();
    }

    float oacc[8][4];
#pragma unroll
    for (int nt = 0; nt < 8; ++nt)
#pragma unroll
        for (int f = 0; f < 4; ++f) oacc[nt][f] = 0.f;
    float m_run[2] = {-INFINITY, -INFINITY};
    float l_part[2] = {0.f, 0.f};

    // ldmatrix lane base offsets (relative to stage / Ps base)
    const int koff = (32*ni + 8*(g8 >> 1) + rw)*KP + 4*(g8 & 1);   // kb nt 0/1
    const int poff = (16*mi + (g8 & 1)*8 + rw)*PP + (g8 >> 1)*4;   // pa
    const int voff = (64*ni + 8*(g8 >> 1) + rw)*VTP + 4*(g8 & 1);  // vb nt 0/1

    for (int ti = 0; ti < numTiles; ++ti) {
        cp_wait<1>();
        __syncthreads();
        if (ti + 2 < numTiles) load_kv((ti + 2) % 3, 64 * (ti + 2));
        cp_commit();

        const unsigned* Kc = sm + (ti % 3) * STG;
        const unsigned* Vc = Kc + K_ST;

        // ---- S = (Q*scale) K^T ----
        float sacc[4][4];
#pragma unroll
        for (int nt = 0; nt < 4; ++nt)
#pragma unroll
            for (int f = 0; f < 4; ++f) sacc[nt][f] = 0.f;

#pragma unroll
        for (int kc = 0; kc < 16; ++kc) {
            unsigned kb[4][2];
            ldm4(kb[0][0], kb[0][1], kb[1][0], kb[1][1], Kc + koff + 8*kc);
            ldm4(kb[2][0], kb[2][1], kb[3][0], kb[3][1], Kc + koff + 16*KP + 8*kc);
#pragma unroll
            for (int nt = 0; nt < 4; ++nt)
                mma8(sacc[nt], qa[kc], kb[nt]);
        }

        // ---- causal mask (diagonal tile only) ----
        if (ti == numTiles - 1) {
#pragma unroll
            for (int nt = 0; nt < 4; ++nt)
#pragma unroll
                for (int f = 0; f < 4; ++f) {
                    int row = lr + ((f >= 2) ? 8 : 0);
                    int col = 32 * ni + 8 * nt + 2 * c + (f & 1);
                    if (col > row) sacc[nt][f] = -1e30f;
                }
        }

        // ---- partial row max, exchange within 2-warp pair ----
        float pmax[2];
#pragma unroll
        for (int h = 0; h < 2; ++h) {
            float mx = -INFINITY;
#pragma unroll
            for (int nt = 0; nt < 4; ++nt) {
                mx = fmaxf(mx, sacc[nt][2 * h]);
                mx = fmaxf(mx, sacc[nt][2 * h + 1]);
            }
            mx = fmaxf(mx, __shfl_xor_sync(0xffffffffu, mx, 1));
            mx = fmaxf(mx, __shfl_xor_sync(0xffffffffu, mx, 2));
            pmax[h] = mx;
        }
        if (c == 0) {
            smax[ni * 64 + lr] = pmax[0];
            smax[ni * 64 + lr + 8] = pmax[1];
        }
        asm volatile("bar.sync %0, 64;" :: "r"(1 + mi));

        float m_new[2], alpha[2];
#pragma unroll
        for (int h = 0; h < 2; ++h) {
            float mt_ = fmaxf(smax[lr + 8 * h], smax[64 + lr + 8 * h]);
            m_new[h] = fmaxf(m_run[h], mt_);
            alpha[h] = __expf(m_run[h] - m_new[h]);
            m_run[h] = m_new[h];
        }

        // ---- exp, write P (tf32), accumulate own-half row sum ----
#pragma unroll
        for (int h = 0; h < 2; ++h) {
            float s_ = 0.f;
#pragma unroll
            for (int nt = 0; nt < 4; ++nt) {
                float p0 = __expf(sacc[nt][2 * h] - m_new[h]);
                float p1 = __expf(sacc[nt][2 * h + 1] - m_new[h]);
                s_ += p0 + p1;
                *(uint2*)&Ps[(lr + 8 * h) * PP + 32 * ni + 8 * nt + 2 * c] =
                    make_uint2(f2tf(p0), f2tf(p1));
            }
            s_ += __shfl_xor_sync(0xffffffffu, s_, 1);
            s_ += __shfl_xor_sync(0xffffffffu, s_, 2);
            l_part[h] = l_part[h] * alpha[h] + s_;
        }

        // ---- rescale O ----
#pragma unroll
        for (int nt = 0; nt < 8; ++nt) {
            oacc[nt][0] *= alpha[0];
            oacc[nt][1] *= alpha[0];
            oacc[nt][2] *= alpha[1];
            oacc[nt][3] *= alpha[1];
        }

        asm volatile("bar.sync %0, 64;" :: "r"(1 + mi));  // P visible to pair

        // ---- O += P V ----
#pragma unroll
        for (int kc2 = 0; kc2 < 8; ++kc2) {
            unsigned pa[4], vb[8][2];
            ldm4(pa[0], pa[1], pa[2], pa[3], Ps + poff + 8*kc2);
            ldm4(vb[0][0], vb[0][1], vb[1][0], vb[1][1], Vc + voff + 8*kc2);
            ldm4(vb[2][0], vb[2][1], vb[3][0], vb[3][1], Vc + voff + 16*VTP + 8*kc2);
            ldm4(vb[4][0], vb[4][1], vb[5][0], vb[5][1], Vc + voff + 32*VTP + 8*kc2);
            ldm4(vb[6][0], vb[6][1], vb[7][0], vb[7][1], Vc + voff + 48*VTP + 8*kc2);
#pragma unroll
            for (int nt = 0; nt < 8; ++nt)
                mma8(oacc[nt], pa, vb[nt]);
        }
    }

    // ---- epilogue: combine l halves, normalize, store ----
    if (c == 0) {
        ssum[ni * 64 + lr] = l_part[0];
        ssum[ni * 64 + lr + 8] = l_part[1];
    }
    asm volatile("bar.sync %0, 64;" :: "r"(1 + mi));
    float inv0 = 1.f / (l_part[0] + ssum[(1 - ni) * 64 + lr]);
    float inv1 = 1.f / (l_part[1] + ssum[(1 - ni) * 64 + lr + 8]);

#pragma unroll
    for (int nt = 0; nt < 8; ++nt) {
        int col = 64 * ni + 8 * nt + 2 * c;
        size_t row0 = base + t0 + lr;
        *(float2*)&out[row0 * DD + col] =
            make_float2(oacc[nt][0] * inv0, oacc[nt][1] * inv0);
        *(float2*)&out[(row0 + 8) * DD + col] =
            make_float2(oacc[nt][2] * inv1, oacc[nt][3] * inv1);
    }
}

// ---------------------------------------------------------------------------
extern "C" void kernel_launch(void* const* d_in, const int* in_sizes, int n_in,
                              void* d_out, int out_size)
{
    (void)in_sizes; (void)n_in; (void)out_size;
    const float* x  = (const float*)d_in[0];
    const float* Wk = (const float*)d_in[1];
    const float* Wq = (const float*)d_in[2];
    const float* Wv = (const float*)d_in[3];
    float* out = (float*)d_out;

    const int NX = BT*EE/4, NW = EE*DD/4;
    const int nCvt = (NX + 3*NW + 255) / 256;
    cvt_kernel<<<nCvt, 256>>>(x, Wk, Wq, Wv);

    const int proj_smem = (3*A_ST + 3*B_ST) * 4;       // 110,592 B
    cudaFuncSetAttribute(proj_kernel,
                         cudaFuncAttributeMaxDynamicSharedMemorySize, proj_smem);
    dim3 pgrid(BT / 128, 3);
    proj_kernel<<<pgrid, 256, proj_smem>>>();

    const int attn_smem = (3*STG + 64*PP + 256) * 4;   // 224,256 B
    cudaFuncSetAttribute(attn_kernel,
                         cudaFuncAttributeMaxDynamicSharedMemorySize, attn_smem);
    attn_kernel<<<TT / 64 * BB, 256, attn_smem>>>(out);
}